// round 10
// baseline (speedup 1.0000x reference)
#include <cuda_runtime.h>
#include <stdint.h>

#define NN   2048          // num_nodes
#define W    64            // words per bitmask row = NN/32
#define FDIM 8             // edge feature dim
#define NB   128           // fused-kernel blocks (16 rows each)

__device__ uint32_t g_adj    [NN * W];   // zero at load; re-zeroed by k_attr
__device__ uint32_t g_comb   [NN * W];
__device__ int      g_wordoff[NN * W];   // global output pos of first bit in word
__device__ unsigned long long g_status[NB];   // lookback: (flag<<32)|count

// ---------------------------------------------------------------------------
// init_idx: fill index region [2, E_MAX] with -1.0f (streaming stores)
// ---------------------------------------------------------------------------
__global__ void k_init_idx(float* __restrict__ out, int emax)
{
    const int64_t n4 = ((int64_t)emax * 2) >> 2;
    const float4 neg = make_float4(-1.f, -1.f, -1.f, -1.f);
    int64_t stride = (int64_t)gridDim.x * blockDim.x;
    for (int64_t i = (int64_t)blockIdx.x * blockDim.x + threadIdx.x;
         i < n4; i += stride)
        __stcs(((float4*)out) + i, neg);
}

// ---------------------------------------------------------------------------
// init_attr: zero attr region [E_MAX, F] (streaming stores, no L2 pollution)
// ---------------------------------------------------------------------------
__global__ void k_init_attr(float* __restrict__ out, int emax)
{
    float* base = out + (int64_t)emax * 2;
    const int64_t n4 = ((int64_t)emax * FDIM) >> 2;
    const float4 zer = make_float4(0.f, 0.f, 0.f, 0.f);
    int64_t stride = (int64_t)gridDim.x * blockDim.x;
    for (int64_t i = (int64_t)blockIdx.x * blockDim.x + threadIdx.x;
         i < n4; i += stride)
        __stcs(((float4*)base) + i, zer);
}

// ---------------------------------------------------------------------------
// scatter: set adjacency bits; also reset lookback statuses for this call
// ---------------------------------------------------------------------------
__global__ void k_scatter(const int* __restrict__ src,
                          const int* __restrict__ dst, int E)
{
    int e = blockIdx.x * blockDim.x + threadIdx.x;
    if (e < NB) g_status[e] = 0ull;
    if (e >= E) return;
    int s = src[e], d = dst[e];
    atomicOr(&g_adj[s * W + (d >> 5)], 1u << (d & 31));
}

// ---------------------------------------------------------------------------
// fused: expand + decoupled-lookback scan + emit. 128 blocks x 256 threads;
// 16 rows per block in 4 batches of 4; thread = (row-in-batch g, word w).
// ---------------------------------------------------------------------------
__global__ __launch_bounds__(256) void k_fused(float* __restrict__ out, int emax)
{
    __shared__ uint16_t nbr[4][NN];
    __shared__ int wtot[4][2];
    __shared__ int etot[4][2];
    __shared__ int rcnt[16];
    __shared__ int sbexcl;

    const int tid  = threadIdx.x;
    const int bid  = blockIdx.x;
    const int g    = tid >> 6;
    const int w    = tid & 63;
    const int lane = w & 31, hw = w >> 5;

    uint32_t comb_reg[4];

    // ---- Phase A: expand 16 rows (4 batches of 4) --------------------------
    #pragma unroll 1
    for (int sub = 0; sub < 4; sub++) {
        const int r = (bid << 4) + (sub << 2) + g;
        uint32_t a = g_adj[r * W + w];

        int pc = __popc(a);
        int x = pc;
        #pragma unroll
        for (int o = 1; o < 32; o <<= 1) {
            int v = __shfl_up_sync(0xffffffffu, x, o);
            if (lane >= o) x += v;
        }
        if (lane == 31) wtot[g][hw] = x;
        __syncthreads();
        int excl = x - pc + (hw ? wtot[g][0] : 0);
        int cnt  = wtot[g][0] + wtot[g][1];

        {
            int p = excl;
            uint32_t m = a;
            while (m) {
                int b = __ffs(m) - 1; m &= m - 1;
                nbr[g][p++] = (uint16_t)((w << 5) + b);
            }
        }
        __syncthreads();

        uint32_t acc = a;
        const uint16_t* nl = nbr[g];
        int j = 0;
        for (; j + 8 <= cnt; j += 8) {
            uint32_t v0 = g_adj[(int)nl[j+0] * W + w];
            uint32_t v1 = g_adj[(int)nl[j+1] * W + w];
            uint32_t v2 = g_adj[(int)nl[j+2] * W + w];
            uint32_t v3 = g_adj[(int)nl[j+3] * W + w];
            uint32_t v4 = g_adj[(int)nl[j+4] * W + w];
            uint32_t v5 = g_adj[(int)nl[j+5] * W + w];
            uint32_t v6 = g_adj[(int)nl[j+6] * W + w];
            uint32_t v7 = g_adj[(int)nl[j+7] * W + w];
            acc |= (v0 | v1) | (v2 | v3) | ((v4 | v5) | (v6 | v7));
        }
        for (; j < cnt; j++)
            acc |= g_adj[(int)nl[j] * W + w];

        uint32_t self = (w == (r >> 5)) ? (1u << (r & 31)) : 0u;
        uint32_t comb = a | (acc & ~self);
        g_comb[r * W + w] = comb;
        comb_reg[sub] = comb;

        int t = __popc(comb);
        #pragma unroll
        for (int o = 16; o; o >>= 1) t += __shfl_down_sync(0xffffffffu, t, o);
        __syncthreads();
        if (lane == 0) wtot[g][hw] = t;
        __syncthreads();
        if (w == 0) rcnt[(sub << 2) + g] = wtot[g][0] + wtot[g][1];
        __syncthreads();
    }

    // ---- Phase B: decoupled lookback (depth <= 4 windows) ------------------
    int bsum = 0;
    #pragma unroll
    for (int q = 0; q < 16; q++) bsum += rcnt[q];

    if (tid == 0) {
        unsigned long long v = bid == 0
            ? ((2ull << 32) | (unsigned)bsum)
            : ((1ull << 32) | (unsigned)bsum);
        atomicExch(&g_status[bid], v);
    }

    if (tid < 32) {
        long long running = 0;
        bool done = (bid == 0);
        int base = bid - 32;
        while (!done) {
            int jj = base + tid;
            unsigned long long s = (jj >= 0)
                ? *(volatile unsigned long long*)&g_status[jj]
                : (2ull << 32);
            unsigned flag = (unsigned)(s >> 32);
            unsigned val  = (unsigned)s;

            unsigned pmask = __ballot_sync(0xffffffffu, flag == 2u);
            unsigned amask = __ballot_sync(0xffffffffu, flag >= 1u);
            if (pmask) {
                int pl = 31 - __clz(pmask);
                unsigned need = 0xffffffffu << pl;
                if ((amask & need) == need) {
                    int contrib = (tid >= pl) ? (int)val : 0;
                    #pragma unroll
                    for (int o = 16; o; o >>= 1)
                        contrib += __shfl_down_sync(0xffffffffu, contrib, o);
                    running += __shfl_sync(0xffffffffu, contrib, 0);
                    done = true;
                }
            } else if (amask == 0xffffffffu) {
                int contrib = (int)val;
                #pragma unroll
                for (int o = 16; o; o >>= 1)
                    contrib += __shfl_down_sync(0xffffffffu, contrib, o);
                running += __shfl_sync(0xffffffffu, contrib, 0);
                base -= 32;
            }
        }
        if (tid == 0) {
            sbexcl = (int)running;
            if (bid != 0)
                atomicExch(&g_status[bid],
                           (2ull << 32) | (unsigned)(running + bsum));
        }
        if (bid == 0 && tid == 0) sbexcl = 0;
    }
    __syncthreads();

    // ---- Phase C: emit 16 rows + publish word offsets ----------------------
    int base_prefix = sbexcl;
    #pragma unroll 1
    for (int sub = 0; sub < 4; sub++) {
        const int r = (bid << 4) + (sub << 2) + g;
        uint32_t comb = comb_reg[sub];

        int row_base = base_prefix;
        #pragma unroll
        for (int q = 0; q < 4; q++) {
            if (q == g) break;
            row_base += rcnt[(sub << 2) + q];
        }

        int epc = __popc(comb);
        int ex = epc;
        #pragma unroll
        for (int o = 1; o < 32; o <<= 1) {
            int v = __shfl_up_sync(0xffffffffu, ex, o);
            if (lane >= o) ex += v;
        }
        if (lane == 31) etot[g][hw] = ex;
        __syncthreads();
        int wexcl = ex - epc + (hw ? etot[g][0] : 0);

        int p = row_base + wexcl;
        g_wordoff[r * W + w] = p;

        float* rows = out;
        float* cols = out + emax;
        float fr = (float)r;
        uint32_t c = comb;
        while (c) {
            int b = __ffs(c) - 1; c &= c - 1;
            if (p >= emax) break;
            rows[p] = fr;
            cols[p] = (float)((w << 5) + b);
            p++;
        }

        #pragma unroll
        for (int q = 0; q < 4; q++) base_prefix += rcnt[(sub << 2) + q];
        __syncthreads();
    }
}

// ---------------------------------------------------------------------------
// attr: O(1) rank via g_wordoff, attr loads issued early; re-zeroes g_adj
// ---------------------------------------------------------------------------
__global__ __launch_bounds__(256) void k_attr(
    const int* __restrict__ src, const int* __restrict__ dst,
    const float* __restrict__ attr, float* __restrict__ out,
    int emax, int E)
{
    int e = blockIdx.x * blockDim.x + threadIdx.x;

    if (e * 4 < NN * W)
        ((uint4*)g_adj)[e] = make_uint4(0u, 0u, 0u, 0u);

    if (e >= E) return;
    int s = src[e], d = dst[e];

    const float4* ia = (const float4*)(attr + (int64_t)e * FDIM);
    float4 a0 = ia[0];
    float4 a1 = ia[1];

    int idx = s * W + (d >> 5);
    int wo  = g_wordoff[idx];
    uint32_t cm = g_comb[idx];

    int p = wo + __popc(cm & ((1u << (d & 31)) - 1u));
    if (p >= emax) return;

    float* oa = out + (int64_t)emax * 2 + (int64_t)p * FDIM;
    asm volatile("red.global.add.v4.f32 [%0], {%1,%2,%3,%4};"
                 :: "l"(oa), "f"(a0.x), "f"(a0.y), "f"(a0.z), "f"(a0.w)
                 : "memory");
    asm volatile("red.global.add.v4.f32 [%0], {%1,%2,%3,%4};"
                 :: "l"(oa + 4), "f"(a1.x), "f"(a1.y), "f"(a1.z), "f"(a1.w)
                 : "memory");
}

// ---------------------------------------------------------------------------
// Host-side resources (host objects only; created once at process start)
// ---------------------------------------------------------------------------
static cudaStream_t s_side;
static cudaEvent_t  ev_fork, ev_idx, ev_attr_init;
struct _ResInit {
    _ResInit() {
        cudaStreamCreateWithFlags(&s_side, cudaStreamNonBlocking);
        cudaEventCreateWithFlags(&ev_fork, cudaEventDisableTiming);
        cudaEventCreateWithFlags(&ev_idx,  cudaEventDisableTiming);
        cudaEventCreateWithFlags(&ev_attr_init, cudaEventDisableTiming);
    }
};
static _ResInit _res_init_once;

extern "C" void kernel_launch(void* const* d_in, const int* in_sizes, int n_in,
                              void* d_out, int out_size)
{
    const int*   ei   = (const int*)d_in[1];
    const float* attr = (const float*)d_in[2];
    const int E    = in_sizes[1] / 2;
    const int emax = out_size / (2 + FDIM);
    float* out = (float*)d_out;

    // side branch: index init (fast) then attr init (big), both overlapped
    cudaEventRecord(ev_fork, 0);
    cudaStreamWaitEvent(s_side, ev_fork, 0);
    k_init_idx <<<768,  256, 0, s_side>>>(out, emax);
    cudaEventRecord(ev_idx, s_side);
    k_init_attr<<<1024, 256, 0, s_side>>>(out, emax);
    cudaEventRecord(ev_attr_init, s_side);

    // main: scatter -> fused (needs idx init only) -> attr (needs attr init)
    k_scatter<<<(E + 255) / 256, 256>>>(ei, ei + E, E);
    cudaStreamWaitEvent(0, ev_idx, 0);
    k_fused<<<NB, 256>>>(out, emax);
    cudaStreamWaitEvent(0, ev_attr_init, 0);
    k_attr<<<(E + 255) / 256, 256>>>(ei, ei + E, attr, out, emax, E);
}

// round 11
// speedup vs baseline: 1.9585x; 1.9585x over previous
#include <cuda_runtime.h>
#include <stdint.h>

#define NN   2048          // num_nodes
#define W    64            // words per bitmask row = NN/32
#define FDIM 8             // edge feature dim

__device__ uint32_t g_adj    [NN * W];   // zero at load; re-zeroed by k_attr
__device__ uint32_t g_comb   [NN * W];
__device__ int      g_rowcnt [NN];
__device__ int      g_wordoff[NN * W];   // global output pos of first bit in word

// ---------------------------------------------------------------------------
// init_idx: fill index region [2, E_MAX] with -1.0f (streaming stores)
// ---------------------------------------------------------------------------
__global__ void k_init_idx(float* __restrict__ out, int emax)
{
    const int64_t n4 = ((int64_t)emax * 2) >> 2;
    const float4 neg = make_float4(-1.f, -1.f, -1.f, -1.f);
    int64_t stride = (int64_t)gridDim.x * blockDim.x;
    for (int64_t i = (int64_t)blockIdx.x * blockDim.x + threadIdx.x;
         i < n4; i += stride)
        __stcs(((float4*)out) + i, neg);
}

// ---------------------------------------------------------------------------
// init_attr: zero attr region [E_MAX, F] (streaming stores)
// ---------------------------------------------------------------------------
__global__ void k_init_attr(float* __restrict__ out, int emax)
{
    float* base = out + (int64_t)emax * 2;
    const int64_t n4 = ((int64_t)emax * FDIM) >> 2;
    const float4 zer = make_float4(0.f, 0.f, 0.f, 0.f);
    int64_t stride = (int64_t)gridDim.x * blockDim.x;
    for (int64_t i = (int64_t)blockIdx.x * blockDim.x + threadIdx.x;
         i < n4; i += stride)
        __stcs(((float4*)base) + i, zer);
}

// ---------------------------------------------------------------------------
// scatter: set adjacency bits
// ---------------------------------------------------------------------------
__global__ void k_scatter(const int* __restrict__ src,
                          const int* __restrict__ dst, int E)
{
    int e = blockIdx.x * blockDim.x + threadIdx.x;
    if (e >= E) return;
    int s = src[e], d = dst[e];
    atomicOr(&g_adj[s * W + (d >> 5)], 1u << (d & 31));
}

// ---------------------------------------------------------------------------
// expand: comb_row = A_row | ((OR over neighbors of A_nbr) & ~self)
// 512 blocks x 256 threads, 4 rows/block; neighbor compaction + MLP-8 ORs.
// Writes g_comb and g_rowcnt.
// ---------------------------------------------------------------------------
__global__ __launch_bounds__(256) void k_expand()
{
    __shared__ uint16_t nbr[4][NN];
    __shared__ int wtot[4][2];

    const int tid  = threadIdx.x;
    const int g    = tid >> 6;
    const int w    = tid & 63;
    const int r    = (blockIdx.x << 2) + g;
    const int lane = w & 31, hw = w >> 5;

    uint32_t a = g_adj[r * W + w];

    int pc = __popc(a);
    int x = pc;
    #pragma unroll
    for (int o = 1; o < 32; o <<= 1) {
        int v = __shfl_up_sync(0xffffffffu, x, o);
        if (lane >= o) x += v;
    }
    if (lane == 31) wtot[g][hw] = x;
    __syncthreads();
    int excl = x - pc + (hw ? wtot[g][0] : 0);
    int cnt  = wtot[g][0] + wtot[g][1];

    {
        int p = excl;
        uint32_t m = a;
        while (m) {
            int b = __ffs(m) - 1; m &= m - 1;
            nbr[g][p++] = (uint16_t)((w << 5) + b);
        }
    }
    __syncthreads();

    uint32_t acc = a;
    const uint16_t* nl = nbr[g];
    int j = 0;
    for (; j + 8 <= cnt; j += 8) {
        uint32_t v0 = g_adj[(int)nl[j+0] * W + w];
        uint32_t v1 = g_adj[(int)nl[j+1] * W + w];
        uint32_t v2 = g_adj[(int)nl[j+2] * W + w];
        uint32_t v3 = g_adj[(int)nl[j+3] * W + w];
        uint32_t v4 = g_adj[(int)nl[j+4] * W + w];
        uint32_t v5 = g_adj[(int)nl[j+5] * W + w];
        uint32_t v6 = g_adj[(int)nl[j+6] * W + w];
        uint32_t v7 = g_adj[(int)nl[j+7] * W + w];
        acc |= (v0 | v1) | (v2 | v3) | ((v4 | v5) | (v6 | v7));
    }
    for (; j < cnt; j++)
        acc |= g_adj[(int)nl[j] * W + w];

    uint32_t self = (w == (r >> 5)) ? (1u << (r & 31)) : 0u;
    uint32_t comb = a | (acc & ~self);
    g_comb[r * W + w] = comb;

    int t = __popc(comb);
    #pragma unroll
    for (int o = 16; o; o >>= 1) t += __shfl_down_sync(0xffffffffu, t, o);
    __syncthreads();
    if (lane == 0) wtot[g][hw] = t;
    __syncthreads();
    if (w == 0) g_rowcnt[r] = wtot[g][0] + wtot[g][1];
}

// ---------------------------------------------------------------------------
// emit: per-block independent prefix (sum rcnt[0..r-1] with 64 threads),
// then word-scan + write (row,col) floats + g_wordoff. No inter-block deps.
// ---------------------------------------------------------------------------
__global__ __launch_bounds__(64) void k_emit(float* __restrict__ out, int emax)
{
    __shared__ int srt[2];     // row-base reduction carries
    __shared__ int etot[2];    // word-scan carry

    const int r    = blockIdx.x;
    const int w    = threadIdx.x;        // 0..63
    const int lane = w & 31, hw = w >> 5;

    // issue own comb word early (independent of the rcnt loop)
    uint32_t comb = g_comb[r * W + w];

    // row_base = sum of g_rowcnt[0..r-1]; strided, independent loads
    int partial = 0;
    for (int i = w; i < r; i += 64)
        partial += g_rowcnt[i];
    #pragma unroll
    for (int o = 16; o; o >>= 1)
        partial += __shfl_down_sync(0xffffffffu, partial, o);
    if (lane == 0) srt[hw] = partial;

    // word-level exclusive scan of popc within the row (overlaps with above)
    int epc = __popc(comb);
    int ex = epc;
    #pragma unroll
    for (int o = 1; o < 32; o <<= 1) {
        int v = __shfl_up_sync(0xffffffffu, ex, o);
        if (lane >= o) ex += v;
    }
    if (lane == 31) etot[hw] = ex;
    __syncthreads();

    int row_base = srt[0] + srt[1];
    int wexcl    = ex - epc + (hw ? etot[0] : 0);

    int p = row_base + wexcl;
    g_wordoff[r * W + w] = p;

    float* rows = out;
    float* cols = out + emax;
    float fr = (float)r;
    uint32_t c = comb;
    while (c) {
        int b = __ffs(c) - 1; c &= c - 1;
        if (p >= emax) break;
        rows[p] = fr;
        cols[p] = (float)((w << 5) + b);
        p++;
    }
}

// ---------------------------------------------------------------------------
// attr: O(1) rank via g_wordoff, attr loads issued early; re-zeroes g_adj
// ---------------------------------------------------------------------------
__global__ __launch_bounds__(256) void k_attr(
    const int* __restrict__ src, const int* __restrict__ dst,
    const float* __restrict__ attr, float* __restrict__ out,
    int emax, int E)
{
    int e = blockIdx.x * blockDim.x + threadIdx.x;

    if (e * 4 < NN * W)
        ((uint4*)g_adj)[e] = make_uint4(0u, 0u, 0u, 0u);

    if (e >= E) return;
    int s = src[e], d = dst[e];

    const float4* ia = (const float4*)(attr + (int64_t)e * FDIM);
    float4 a0 = ia[0];
    float4 a1 = ia[1];

    int idx = s * W + (d >> 5);
    int wo  = g_wordoff[idx];
    uint32_t cm = g_comb[idx];

    int p = wo + __popc(cm & ((1u << (d & 31)) - 1u));
    if (p >= emax) return;

    float* oa = out + (int64_t)emax * 2 + (int64_t)p * FDIM;
    asm volatile("red.global.add.v4.f32 [%0], {%1,%2,%3,%4};"
                 :: "l"(oa), "f"(a0.x), "f"(a0.y), "f"(a0.z), "f"(a0.w)
                 : "memory");
    asm volatile("red.global.add.v4.f32 [%0], {%1,%2,%3,%4};"
                 :: "l"(oa + 4), "f"(a1.x), "f"(a1.y), "f"(a1.z), "f"(a1.w)
                 : "memory");
}

// ---------------------------------------------------------------------------
// Host-side resources (host objects only; created once at process start)
// ---------------------------------------------------------------------------
static cudaStream_t s_side;
static cudaEvent_t  ev_fork, ev_idx, ev_attr_init;
struct _ResInit {
    _ResInit() {
        cudaStreamCreateWithFlags(&s_side, cudaStreamNonBlocking);
        cudaEventCreateWithFlags(&ev_fork, cudaEventDisableTiming);
        cudaEventCreateWithFlags(&ev_idx,  cudaEventDisableTiming);
        cudaEventCreateWithFlags(&ev_attr_init, cudaEventDisableTiming);
    }
};
static _ResInit _res_init_once;

extern "C" void kernel_launch(void* const* d_in, const int* in_sizes, int n_in,
                              void* d_out, int out_size)
{
    const int*   ei   = (const int*)d_in[1];
    const float* attr = (const float*)d_in[2];
    const int E    = in_sizes[1] / 2;
    const int emax = out_size / (2 + FDIM);
    float* out = (float*)d_out;

    // side branch: index init (fast) then attr init (big), both overlapped
    cudaEventRecord(ev_fork, 0);
    cudaStreamWaitEvent(s_side, ev_fork, 0);
    k_init_idx <<<768,  256, 0, s_side>>>(out, emax);
    cudaEventRecord(ev_idx, s_side);
    k_init_attr<<<1024, 256, 0, s_side>>>(out, emax);
    cudaEventRecord(ev_attr_init, s_side);

    // main: scatter -> expand -> emit (needs idx init) -> attr (needs attr init)
    k_scatter<<<(E + 255) / 256, 256>>>(ei, ei + E, E);
    k_expand <<<NN / 4, 256>>>();
    cudaStreamWaitEvent(0, ev_idx, 0);
    k_emit   <<<NN, 64>>>(out, emax);
    cudaStreamWaitEvent(0, ev_attr_init, 0);
    k_attr   <<<(E + 255) / 256, 256>>>(ei, ei + E, attr, out, emax, E);
}

// round 12
// speedup vs baseline: 2.1548x; 1.1003x over previous
#include <cuda_runtime.h>
#include <stdint.h>

#define NN    2048         // num_nodes
#define W     64           // words per bitmask row = NN/32
#define FDIM  8            // edge feature dim
#define TAILB 256          // tail-fill blocks appended to k_emit's grid

__device__ uint32_t g_adj    [NN * W];   // zero at load; re-zeroed by k_attr
__device__ uint32_t g_comb   [NN * W];
__device__ int      g_rowcnt [NN];
__device__ int      g_wordoff[NN * W];   // global output pos of first bit in word

// ---------------------------------------------------------------------------
// init_attr: zero attr region [E_MAX, F] (streaming stores; gates only k_attr)
// ---------------------------------------------------------------------------
__global__ void k_init_attr(float* __restrict__ out, int emax)
{
    float* base = out + (int64_t)emax * 2;
    const int64_t n4 = ((int64_t)emax * FDIM) >> 2;
    const float4 zer = make_float4(0.f, 0.f, 0.f, 0.f);
    int64_t stride = (int64_t)gridDim.x * blockDim.x;
    for (int64_t i = (int64_t)blockIdx.x * blockDim.x + threadIdx.x;
         i < n4; i += stride)
        __stcs(((float4*)base) + i, zer);
}

// ---------------------------------------------------------------------------
// scatter: set adjacency bits
// ---------------------------------------------------------------------------
__global__ void k_scatter(const int* __restrict__ src,
                          const int* __restrict__ dst, int E)
{
    int e = blockIdx.x * blockDim.x + threadIdx.x;
    if (e >= E) return;
    int s = src[e], d = dst[e];
    atomicOr(&g_adj[s * W + (d >> 5)], 1u << (d & 31));
}

// ---------------------------------------------------------------------------
// expand: comb_row = A_row | ((OR over neighbors of A_nbr) & ~self)
// 512 blocks x 256 threads, 4 rows/block; neighbor compaction + MLP-8 ORs.
// ---------------------------------------------------------------------------
__global__ __launch_bounds__(256) void k_expand()
{
    __shared__ uint16_t nbr[4][NN];
    __shared__ int wtot[4][2];

    const int tid  = threadIdx.x;
    const int g    = tid >> 6;
    const int w    = tid & 63;
    const int r    = (blockIdx.x << 2) + g;
    const int lane = w & 31, hw = w >> 5;

    uint32_t a = g_adj[r * W + w];

    int pc = __popc(a);
    int x = pc;
    #pragma unroll
    for (int o = 1; o < 32; o <<= 1) {
        int v = __shfl_up_sync(0xffffffffu, x, o);
        if (lane >= o) x += v;
    }
    if (lane == 31) wtot[g][hw] = x;
    __syncthreads();
    int excl = x - pc + (hw ? wtot[g][0] : 0);
    int cnt  = wtot[g][0] + wtot[g][1];

    {
        int p = excl;
        uint32_t m = a;
        while (m) {
            int b = __ffs(m) - 1; m &= m - 1;
            nbr[g][p++] = (uint16_t)((w << 5) + b);
        }
    }
    __syncthreads();

    uint32_t acc = a;
    const uint16_t* nl = nbr[g];
    int j = 0;
    for (; j + 8 <= cnt; j += 8) {
        uint32_t v0 = g_adj[(int)nl[j+0] * W + w];
        uint32_t v1 = g_adj[(int)nl[j+1] * W + w];
        uint32_t v2 = g_adj[(int)nl[j+2] * W + w];
        uint32_t v3 = g_adj[(int)nl[j+3] * W + w];
        uint32_t v4 = g_adj[(int)nl[j+4] * W + w];
        uint32_t v5 = g_adj[(int)nl[j+5] * W + w];
        uint32_t v6 = g_adj[(int)nl[j+6] * W + w];
        uint32_t v7 = g_adj[(int)nl[j+7] * W + w];
        acc |= (v0 | v1) | (v2 | v3) | ((v4 | v5) | (v6 | v7));
    }
    for (; j < cnt; j++)
        acc |= g_adj[(int)nl[j] * W + w];

    uint32_t self = (w == (r >> 5)) ? (1u << (r & 31)) : 0u;
    uint32_t comb = a | (acc & ~self);
    g_comb[r * W + w] = comb;

    int t = __popc(comb);
    #pragma unroll
    for (int o = 16; o; o >>= 1) t += __shfl_down_sync(0xffffffffu, t, o);
    __syncthreads();
    if (lane == 0) wtot[g][hw] = t;
    __syncthreads();
    if (w == 0) g_rowcnt[r] = wtot[g][0] + wtot[g][1];
}

// ---------------------------------------------------------------------------
// emit: blocks [0,NN)   -> per-row prefix + write (row,col) + g_wordoff
//       blocks [NN,+TAILB) -> compute count, fill idx tail [count,emax) = -1
// No dependency on any init kernel.
// ---------------------------------------------------------------------------
__global__ __launch_bounds__(64) void k_emit(float* __restrict__ out, int emax)
{
    __shared__ int srt[2];
    __shared__ int etot[2];

    const int bid  = blockIdx.x;
    const int w    = threadIdx.x;        // 0..63
    const int lane = w & 31, hw = w >> 5;

    float* rows = out;
    float* cols = out + emax;

    if (bid >= NN) {
        // ---- tail fill: idx region [count, emax) = -1 ----------------------
        int partial = 0;
        for (int i = w; i < NN; i += 64)
            partial += g_rowcnt[i];
        #pragma unroll
        for (int o = 16; o; o >>= 1)
            partial += __shfl_down_sync(0xffffffffu, partial, o);
        if (lane == 0) srt[hw] = partial;
        __syncthreads();
        int total = srt[0] + srt[1];

        int tb    = bid - NN;
        int len   = emax - total;
        int chunk = (len + TAILB - 1) / TAILB;
        int b0    = total + tb * chunk;
        int b1    = b0 + chunk; if (b1 > emax) b1 = emax;
        for (int i = b0 + w; i < b1; i += 64) {
            rows[i] = -1.f;
            cols[i] = -1.f;
        }
        return;
    }

    const int r = bid;
    uint32_t comb = g_comb[r * W + w];

    // row_base = sum of g_rowcnt[0..r-1]
    int partial = 0;
    for (int i = w; i < r; i += 64)
        partial += g_rowcnt[i];
    #pragma unroll
    for (int o = 16; o; o >>= 1)
        partial += __shfl_down_sync(0xffffffffu, partial, o);
    if (lane == 0) srt[hw] = partial;

    // word-level exclusive scan of popc within the row
    int epc = __popc(comb);
    int ex = epc;
    #pragma unroll
    for (int o = 1; o < 32; o <<= 1) {
        int v = __shfl_up_sync(0xffffffffu, ex, o);
        if (lane >= o) ex += v;
    }
    if (lane == 31) etot[hw] = ex;
    __syncthreads();

    int row_base = srt[0] + srt[1];
    int wexcl    = ex - epc + (hw ? etot[0] : 0);

    int p = row_base + wexcl;
    g_wordoff[r * W + w] = p;

    float fr = (float)r;
    uint32_t c = comb;
    while (c) {
        int b = __ffs(c) - 1; c &= c - 1;
        if (p >= emax) break;
        rows[p] = fr;
        cols[p] = (float)((w << 5) + b);
        p++;
    }
}

// ---------------------------------------------------------------------------
// attr: O(1) rank via g_wordoff, attr loads issued early; re-zeroes g_adj
// ---------------------------------------------------------------------------
__global__ __launch_bounds__(256) void k_attr(
    const int* __restrict__ src, const int* __restrict__ dst,
    const float* __restrict__ attr, float* __restrict__ out,
    int emax, int E)
{
    int e = blockIdx.x * blockDim.x + threadIdx.x;

    if (e * 4 < NN * W)
        ((uint4*)g_adj)[e] = make_uint4(0u, 0u, 0u, 0u);

    if (e >= E) return;
    int s = src[e], d = dst[e];

    const float4* ia = (const float4*)(attr + (int64_t)e * FDIM);
    float4 a0 = ia[0];
    float4 a1 = ia[1];

    int idx = s * W + (d >> 5);
    int wo  = g_wordoff[idx];
    uint32_t cm = g_comb[idx];

    int p = wo + __popc(cm & ((1u << (d & 31)) - 1u));
    if (p >= emax) return;

    float* oa = out + (int64_t)emax * 2 + (int64_t)p * FDIM;
    asm volatile("red.global.add.v4.f32 [%0], {%1,%2,%3,%4};"
                 :: "l"(oa), "f"(a0.x), "f"(a0.y), "f"(a0.z), "f"(a0.w)
                 : "memory");
    asm volatile("red.global.add.v4.f32 [%0], {%1,%2,%3,%4};"
                 :: "l"(oa + 4), "f"(a1.x), "f"(a1.y), "f"(a1.z), "f"(a1.w)
                 : "memory");
}

// ---------------------------------------------------------------------------
// Host-side resources (host objects only; created once at process start)
// ---------------------------------------------------------------------------
static cudaStream_t s_side;
static cudaEvent_t  ev_fork, ev_attr_init;
struct _ResInit {
    _ResInit() {
        cudaStreamCreateWithFlags(&s_side, cudaStreamNonBlocking);
        cudaEventCreateWithFlags(&ev_fork, cudaEventDisableTiming);
        cudaEventCreateWithFlags(&ev_attr_init, cudaEventDisableTiming);
    }
};
static _ResInit _res_init_once;

extern "C" void kernel_launch(void* const* d_in, const int* in_sizes, int n_in,
                              void* d_out, int out_size)
{
    const int*   ei   = (const int*)d_in[1];
    const float* attr = (const float*)d_in[2];
    const int E    = in_sizes[1] / 2;
    const int emax = out_size / (2 + FDIM);
    float* out = (float*)d_out;

    // side branch: attr-region zero fill (gates only k_attr)
    cudaEventRecord(ev_fork, 0);
    cudaStreamWaitEvent(s_side, ev_fork, 0);
    k_init_attr<<<1024, 256, 0, s_side>>>(out, emax);
    cudaEventRecord(ev_attr_init, s_side);

    // main: scatter -> expand -> emit(+tail fill) -> attr (after attr init)
    k_scatter<<<(E + 255) / 256, 256>>>(ei, ei + E, E);
    k_expand <<<NN / 4, 256>>>();
    k_emit   <<<NN + TAILB, 64>>>(out, emax);
    cudaStreamWaitEvent(0, ev_attr_init, 0);
    k_attr   <<<(E + 255) / 256, 256>>>(ei, ei + E, attr, out, emax, E);
}